// round 10
// baseline (speedup 1.0000x reference)
#include <cuda_runtime.h>
#include <cuda_fp16.h>
#include <math.h>

#define XD 128
#define NDEPTH 222
#define MPAD 240
// max_extent = sqrt(3*(64^2)) * 1.5
static constexpr double MAX_EXTENT_D = 166.27687752661222232;
static constexpr double DT_D         = 2.0 * MAX_EXTENT_D / (NDEPTH - 1);
static constexpr double SCALE_D      = 2.0 * MAX_EXTENT_D / NDEPTH;

// fp16 copy of the volume (scratch; rebuilt every launch).
// 128^3 halves = 2,097,152 halves = 524,288 uint2 (4 halves each) = 4 MB.
__device__ uint2 g_volh[XD * XD * XD / 4];

__global__ void __launch_bounds__(256)
convert_kernel(const float* __restrict__ vol) {
    const int i = blockIdx.x * 256 + threadIdx.x;   // one uint2 (4 halves) per thread
    const float4 v = __ldg((const float4*)vol + i);
    uint2 q;
    __half2 a = __floats2half2_rn(v.x, v.y);
    __half2 b = __floats2half2_rn(v.z, v.w);
    q.x = *(const unsigned*)&a;
    q.y = *(const unsigned*)&b;
    g_volh[i] = q;
}

__device__ __forceinline__ void slab_axis(float r, float b, float& tlo, float& thi, bool& empty) {
    if (fabsf(r) > 1e-12f) {
        float inv = __frcp_rn(r);
        float ta = (-1.0f - b) * inv;
        float tb = (128.0f - b) * inv;
        tlo = fmaxf(tlo, fminf(ta, tb));
        thi = fminf(thi, fmaxf(ta, tb));
    } else if (b <= -1.0f || b >= 128.0f) {
        empty = true;
    }
}

__device__ __forceinline__ void acc_row(float4& S, float wt, uint2 q) {
    const float2 f01 = __half22float2(*reinterpret_cast<const __half2*>(&q.x));
    const float2 f23 = __half22float2(*reinterpret_cast<const __half2*>(&q.y));
    S.x = fmaf(wt, f01.x, S.x);
    S.y = fmaf(wt, f01.y, S.y);
    S.z = fmaf(wt, f23.x, S.z);
    S.w = fmaf(wt, f23.y, S.w);
}

__global__ void __launch_bounds__(128, 8)
projector_kernel(const float* __restrict__ vol,
                 const float* __restrict__ vec,
                 float* __restrict__ out) {
    const int tid = threadIdx.x;
    const int j   = blockIdx.x;
    const int n   = blockIdx.y;

    const float* V = vec + n * 12;
    const float rx = __ldg(V + 0), ry = __ldg(V + 1), rz = __ldg(V + 2);
    const float dx = __ldg(V + 3), dy = __ldg(V + 4), dz = __ldg(V + 5);
    const float ux = __ldg(V + 6), uy = __ldg(V + 7), uz = __ldg(V + 8);
    const float vx = __ldg(V + 9), vy = __ldg(V + 10), vz = __ldg(V + 11);

    const float t0 = (float)(-MAX_EXTENT_D);
    const float dt = (float)DT_D;
    const float jc = (float)j - 63.5f;

    __shared__ int4   As[MPAD];    // byte offsets of the 4 rows (fp16 rows: 256B stride)
    __shared__ float4 Ws[MPAD];    // bilinear weights
    __shared__ float  Red[4][132]; // padded reduce buffer

    // Fast path: z-axis-aligned geometry -> per-block-uniform (x,y) sample,
    // z index is EXACTLY the pixel k with fz = 0 (single z-tap, weight 1).
    const bool fast = (rz == 0.0f) & (uz == 0.0f) & (dz == 0.0f) &
                      (vx == 0.0f) & (vy == 0.0f) & (vz == 1.0f);

    if (fast) {
        const int w    = tid >> 5;   // warp id (0..3)
        const int lane = tid & 31;   // covers z = 4*lane .. 4*lane+3

        const float bx = fmaf(jc, ux, dx) + 63.5f;
        const float by = fmaf(jc, uy, dy) + 63.5f;

        float tlo = -3.0e38f, thi = 3.0e38f;
        bool empty = false;
        slab_axis(rx, bx, tlo, thi, empty);
        slab_axis(ry, by, tlo, thi, empty);

        int i0 = 0, cnt = 0;
        if (!empty && thi >= tlo) {
            i0 = max(0, (int)ceilf((tlo - t0) / dt) - 1);
            int i1 = min(NDEPTH - 1, (int)floorf((thi - t0) / dt) + 1);
            cnt = i1 - i0 + 1;
            if (cnt < 0) cnt = 0;
        }
        const int cntPad = (cnt + 15) & ~15;   // 4 warps x unroll-4 granularity

        // Metadata phase: per-step row byte-offsets (fp16 rows) + weights.
        for (int m = tid; m < cntPad; m += 128) {
            if (m < cnt) {
                const float t  = fmaf((float)(i0 + m), dt, t0);
                const float px = fmaf(t, rx, bx);
                const float py = fmaf(t, ry, by);
                const float x0f = floorf(px);
                const float y0f = floorf(py);
                const float fx = px - x0f;
                const float fy = py - y0f;
                const int x0 = (int)x0f;
                const int y0 = (int)y0f;
                const float wx0 = ((unsigned)x0       < (unsigned)XD) ? (1.0f - fx) : 0.0f;
                const float wx1 = ((unsigned)(x0 + 1) < (unsigned)XD) ? fx          : 0.0f;
                const float wy0 = ((unsigned)y0       < (unsigned)XD) ? (1.0f - fy) : 0.0f;
                const float wy1 = ((unsigned)(y0 + 1) < (unsigned)XD) ? fy          : 0.0f;
                const int xc0 = min(max(x0, 0), XD - 1);
                const int xc1 = min(max(x0 + 1, 0), XD - 1);
                const int yc0 = min(max(y0, 0), XD - 1);
                const int yc1 = min(max(y0 + 1, 0), XD - 1);
                As[m] = make_int4((xc0 * XD + yc0) << 8, (xc0 * XD + yc1) << 8,
                                  (xc1 * XD + yc0) << 8, (xc1 * XD + yc1) << 8);
                Ws[m] = make_float4(wx0 * wy0, wx0 * wy1, wx1 * wy0, wx1 * wy1);
            } else {
                As[m] = make_int4(0, 0, 0, 0);
                Ws[m] = make_float4(0.0f, 0.0f, 0.0f, 0.0f);
            }
        }
        __syncthreads();

        // Mainloop: 4 steps per trip per warp -> 16 x LDG.64 in flight + 64 FFMA.
        const char* volb = (const char*)g_volh + (lane << 3);
        float4 S = make_float4(0.0f, 0.0f, 0.0f, 0.0f);
        for (int m = 4 * w; m < cntPad; m += 16) {
            const int4   A0 = As[m];
            const int4   A1 = As[m + 1];
            const int4   A2 = As[m + 2];
            const int4   A3 = As[m + 3];
            const float4 W0 = Ws[m];
            const float4 W1 = Ws[m + 1];
            const float4 W2 = Ws[m + 2];
            const float4 W3 = Ws[m + 3];
            const uint2 q00 = __ldg((const uint2*)(volb + A0.x));
            const uint2 q01 = __ldg((const uint2*)(volb + A0.y));
            const uint2 q02 = __ldg((const uint2*)(volb + A0.z));
            const uint2 q03 = __ldg((const uint2*)(volb + A0.w));
            const uint2 q10 = __ldg((const uint2*)(volb + A1.x));
            const uint2 q11 = __ldg((const uint2*)(volb + A1.y));
            const uint2 q12 = __ldg((const uint2*)(volb + A1.z));
            const uint2 q13 = __ldg((const uint2*)(volb + A1.w));
            const uint2 q20 = __ldg((const uint2*)(volb + A2.x));
            const uint2 q21 = __ldg((const uint2*)(volb + A2.y));
            const uint2 q22 = __ldg((const uint2*)(volb + A2.z));
            const uint2 q23 = __ldg((const uint2*)(volb + A2.w));
            const uint2 q30 = __ldg((const uint2*)(volb + A3.x));
            const uint2 q31 = __ldg((const uint2*)(volb + A3.y));
            const uint2 q32 = __ldg((const uint2*)(volb + A3.z));
            const uint2 q33 = __ldg((const uint2*)(volb + A3.w));
            acc_row(S, W0.x, q00); acc_row(S, W0.y, q01);
            acc_row(S, W0.z, q02); acc_row(S, W0.w, q03);
            acc_row(S, W1.x, q10); acc_row(S, W1.y, q11);
            acc_row(S, W1.z, q12); acc_row(S, W1.w, q13);
            acc_row(S, W2.x, q20); acc_row(S, W2.y, q21);
            acc_row(S, W2.z, q22); acc_row(S, W2.w, q23);
            acc_row(S, W3.x, q30); acc_row(S, W3.y, q31);
            acc_row(S, W3.z, q32); acc_row(S, W3.w, q33);
        }
        Red[w][lane * 4 + 0] = S.x;
        Red[w][lane * 4 + 1] = S.y;
        Red[w][lane * 4 + 2] = S.z;
        Red[w][lane * 4 + 3] = S.w;
        __syncthreads();

        const float acc = Red[0][tid] + Red[1][tid] + Red[2][tid] + Red[3][tid];
        out[((n * XD) + j) * XD + tid] = acc * (float)SCALE_D;
    } else {
        // General path: per-pixel trilinear gather from the ORIGINAL fp32 volume.
        const int z = tid;
        const float kc = (float)z - 63.5f;
        const float bx = fmaf(kc, vx, fmaf(jc, ux, dx)) + 63.5f;
        const float by = fmaf(kc, vy, fmaf(jc, uy, dy)) + 63.5f;
        const float bz = fmaf(kc, vz, fmaf(jc, uz, dz)) + 63.5f;

        float tlo = -3.0e38f, thi = 3.0e38f;
        bool empty = false;
        slab_axis(rx, bx, tlo, thi, empty);
        slab_axis(ry, by, tlo, thi, empty);
        slab_axis(rz, bz, tlo, thi, empty);

        int i0 = 0, i1 = -1;
        if (!empty && thi >= tlo) {
            i0 = max(0, (int)ceilf((tlo - t0) / dt) - 1);
            i1 = min(NDEPTH - 1, (int)floorf((thi - t0) / dt) + 1);
        }

        float sum = 0.0f;
        for (int i = i0; i <= i1; ++i) {
            const float t  = fmaf((float)i, dt, t0);
            const float px = fmaf(t, rx, bx);
            const float py = fmaf(t, ry, by);
            const float pz = fmaf(t, rz, bz);

            const float x0f = floorf(px);
            const float y0f = floorf(py);
            const float z0f = floorf(pz);
            const float fx = px - x0f;
            const float fy = py - y0f;
            const float fz = pz - z0f;
            const int x0 = (int)x0f;
            const int y0 = (int)y0f;
            const int z0 = (int)z0f;

            const int a = x0 * (XD * XD) + y0 * XD + z0;

            const bool xv0 = ((unsigned)x0 < (unsigned)XD);
            const bool xv1 = ((unsigned)(x0 + 1) < (unsigned)XD);
            const bool yv0 = ((unsigned)y0 < (unsigned)XD);
            const bool yv1 = ((unsigned)(y0 + 1) < (unsigned)XD);
            const bool zv0 = ((unsigned)z0 < (unsigned)XD);
            const bool zv1 = ((unsigned)(z0 + 1) < (unsigned)XD);

            const float v000 = (xv0 & yv0 & zv0) ? __ldg(vol + a)                    : 0.0f;
            const float v001 = (xv0 & yv0 & zv1) ? __ldg(vol + a + 1)                : 0.0f;
            const float v010 = (xv0 & yv1 & zv0) ? __ldg(vol + a + XD)               : 0.0f;
            const float v011 = (xv0 & yv1 & zv1) ? __ldg(vol + a + XD + 1)           : 0.0f;
            const float v100 = (xv1 & yv0 & zv0) ? __ldg(vol + a + XD * XD)          : 0.0f;
            const float v101 = (xv1 & yv0 & zv1) ? __ldg(vol + a + XD * XD + 1)      : 0.0f;
            const float v110 = (xv1 & yv1 & zv0) ? __ldg(vol + a + XD * XD + XD)     : 0.0f;
            const float v111 = (xv1 & yv1 & zv1) ? __ldg(vol + a + XD * XD + XD + 1) : 0.0f;

            const float c00 = fmaf(fz, v001 - v000, v000);
            const float c01 = fmaf(fz, v011 - v010, v010);
            const float c10 = fmaf(fz, v101 - v100, v100);
            const float c11 = fmaf(fz, v111 - v110, v110);
            const float c0  = fmaf(fy, c01 - c00, c00);
            const float c1  = fmaf(fy, c11 - c10, c10);
            sum += fmaf(fx, c1 - c0, c0);
        }
        out[((n * XD) + j) * XD + z] = sum * (float)SCALE_D;
    }
}

extern "C" void kernel_launch(void* const* d_in, const int* in_sizes, int n_in,
                              void* d_out, int out_size) {
    const float* vol = (const float*)d_in[0];
    const float* vec = (const float*)d_in[1];
    float* out = (float*)d_out;

    const int N = in_sizes[1] / 12;
    convert_kernel<<<XD * XD * XD / 4 / 256, 256>>>(vol);
    dim3 grid(XD, N);
    dim3 block(128);
    projector_kernel<<<grid, block>>>(vol, vec, out);
}